// round 13
// baseline (speedup 1.0000x reference)
#include <cuda_runtime.h>
#include <cuda_bf16.h>

#define HH 256
#define WW 256
#define NIMG (64*21)
#define TILE_X 128
#define TILE_Y 32
#define HROWS (TILE_Y + 8)   // 40 horizontal-filtered rows
#define HSTRIDE 128          // h tile = exactly the output columns

// Packed f32x2 FMA (Blackwell FFMA2) — ptxas never emits this from C++.
__device__ __forceinline__ float2 ffma2(float2 a, float2 b, float2 c) {
    float2 d;
    asm("fma.rn.f32x2 %0, %1, %2, %3;"
        : "=l"(reinterpret_cast<unsigned long long&>(d))
        : "l"(reinterpret_cast<unsigned long long&>(a)),
          "l"(reinterpret_cast<unsigned long long&>(b)),
          "l"(reinterpret_cast<unsigned long long&>(c)));
    return d;
}

// Gaussian symmetric: g[j] == g[8-j] bit-exactly (row sums of symmetric kernel).
#define GSYM(j) gs[((j) < 5) ? (j) : (8 - (j))]
#define GG(j)   gg[((j) < 5) ? (j) : (8 - (j))]

__global__ __launch_bounds__(256, 6)
void heatmap_sepconv_kernel(const int* __restrict__ coords,
                            const float* __restrict__ noise,
                            const float* __restrict__ k2d,
                            float* __restrict__ out)
{
    __shared__ float sk[81];
    __shared__ __align__(16) float hs[HROWS * HSTRIDE];  // 20480 B

    const int tid = threadIdx.x;
    const int img = blockIdx.z;
    const int x0 = blockIdx.x * TILE_X;
    const int y0 = blockIdx.y * TILE_Y;

    if (tid < 81) sk[tid] = k2d[tid];
    __syncthreads();

    // 5 scalar symmetric taps (row sums of the 2D kernel).
    float gs[5];
    #pragma unroll
    for (int i = 0; i < 5; i++) {
        float s = 0.f;
        #pragma unroll
        for (int j = 0; j < 9; j++) s += sk[i * 9 + j];
        gs[i] = s;
    }

    const float* __restrict__ np = noise + (size_t)img * (HH * WW);

    // ============ Phase 1: horizontal pass, gmem -> registers -> h smem =======
    // Warp w sweeps full rows: row = s*8 + w; lanes cover 32 aligned float4 groups.
    {
        const int lane = tid & 31;
        const int w = tid >> 5;
        const int cb = lane << 2;            // local output col group 0..124
        #pragma unroll
        for (int s = 0; s < 5; s++) {
            const int row = s * 8 + w;       // 0..39
            const int gy = y0 - 4 + row;
            float h0 = 0.f, h1 = 0.f, h2 = 0.f, h3 = 0.f;
            if (gy >= 0 && gy < HH) {
                const float* rowp = np + gy * WW;
                const int gxl = x0 + cb - 4;
                const int gxr = x0 + cb + 4;
                float4 L = (gxl >= 0) ? *(const float4*)(rowp + gxl)
                                      : make_float4(0.f, 0.f, 0.f, 0.f);
                float4 C = *(const float4*)(rowp + x0 + cb);
                float4 R = (gxr + 3 < WW) ? *(const float4*)(rowp + gxr)
                                          : make_float4(0.f, 0.f, 0.f, 0.f);
                float v[12] = {L.x, L.y, L.z, L.w, C.x, C.y, C.z, C.w,
                               R.x, R.y, R.z, R.w};
                #pragma unroll
                for (int j = 0; j < 9; j++) {
                    const float gj = GSYM(j);
                    h0 = fmaf(gj, v[j],     h0);
                    h1 = fmaf(gj, v[j + 1], h1);
                    h2 = fmaf(gj, v[j + 2], h2);
                    h3 = fmaf(gj, v[j + 3], h3);
                }
            }
            *(float4*)&hs[row * HSTRIDE + cb] = make_float4(h0, h1, h2, h3);
        }
    }
    __syncthreads();

    // ============ Peak injection into the h tile (exact, by linearity) ========
    // Replacing noise[cy][cx] with the peak changes h[cy][c] by delta*g[c-cx+4]
    // for c in [cx-4, cx+4]. 9 threads patch the h rows this tile computed.
    if (tid < 9) {
        const int cx = coords[2 * img];
        const int cy = coords[2 * img + 1];
        const int ly = cy - y0 + 4;              // h-tile row of the peak
        const int lcol = cx - 4 + tid - x0;      // h-tile col this thread patches
        if (ly >= 0 && ly < HROWS && lcol >= 0 && lcol < HSTRIDE) {
            float gtap = 0.f;
            #pragma unroll
            for (int jj = 0; jj < 9; jj++) gtap += sk[tid * 9 + jj];
            const float delta = 100.0f / sk[40] - np[cy * WW + cx];
            hs[ly * HSTRIDE + lcol] += delta * gtap;
        }
    }
    __syncthreads();

    // ============ Phase 2: vertical pass from h smem, FFMA2 ===================
    float2 gg[5];
    #pragma unroll
    for (int i = 0; i < 5; i++) gg[i] = make_float2(gs[i], gs[i]);

    const int g  = tid & 63;        // column pair: output cols 2g, 2g+1
    const int ty = tid >> 6;        // 0..3
    const int r0 = ty << 3;         // first output row (8 per thread)

    float2 A[8];
    #pragma unroll
    for (int r = 0; r < 8; r++) A[r] = make_float2(0.f, 0.f);

    // Stream 16 h rows; each LDS.64 is a direct FFMA2 operand (no packing).
    const float* hp = &hs[r0 * HSTRIDE + 2 * g];
    #pragma unroll
    for (int ir = 0; ir < 16; ir++) {
        const float2 hv = *(const float2*)(hp);
        hp += HSTRIDE;
        #pragma unroll
        for (int r = 0; r < 8; r++) {
            const int j = ir - r;
            if (j >= 0 && j <= 8) A[r] = ffma2(GG(j), hv, A[r]);
        }
    }

    // Store: deferred 0.01 scale + ReLU; STG.64 fully coalesced.
    float* op = out + (size_t)img * (HH * WW) + (size_t)(y0 + r0) * WW + x0 + 2 * g;
    #pragma unroll
    for (int r = 0; r < 8; r++) {
        float2 ov = make_float2(fmaxf(A[r].x, 0.f) * 0.01f,
                                fmaxf(A[r].y, 0.f) * 0.01f);
        *(float2*)op = ov;
        op += WW;
    }
}

extern "C" void kernel_launch(void* const* d_in, const int* in_sizes, int n_in,
                              void* d_out, int out_size)
{
    const int* coords = nullptr;
    const float* noise = nullptr;
    const float* k2d = nullptr;
    for (int i = 0; i < n_in; i++) {
        if (in_sizes[i] == 81)            k2d    = (const float*)d_in[i];
        else if (in_sizes[i] == 64*21*2)  coords = (const int*)d_in[i];
        else                              noise  = (const float*)d_in[i];
    }

    dim3 grid(WW / TILE_X, HH / TILE_Y, NIMG);
    heatmap_sepconv_kernel<<<grid, 256>>>(coords, noise, k2d, (float*)d_out);
}

// round 14
// speedup vs baseline: 1.2655x; 1.2655x over previous
#include <cuda_runtime.h>
#include <cuda_bf16.h>

#define HH 256
#define WW 256
#define NIMG (64*21)
#define TILE_X 128
#define TILE_Y 64
#define HROWS (TILE_Y + 8)   // 72 horizontal-filtered rows
#define HSTRIDE 128          // h tile = exactly the output columns
#define NTHR 512

// Packed f32x2 FMA (Blackwell FFMA2) — ptxas never emits this from C++.
__device__ __forceinline__ float2 ffma2(float2 a, float2 b, float2 c) {
    float2 d;
    asm("fma.rn.f32x2 %0, %1, %2, %3;"
        : "=l"(reinterpret_cast<unsigned long long&>(d))
        : "l"(reinterpret_cast<unsigned long long&>(a)),
          "l"(reinterpret_cast<unsigned long long&>(b)),
          "l"(reinterpret_cast<unsigned long long&>(c)));
    return d;
}

// Gaussian symmetric: g[j] == g[8-j] bit-exactly (row sums of symmetric kernel).
#define GSYM(j) gs[((j) < 5) ? (j) : (8 - (j))]
#define GG(j)   gg[((j) < 5) ? (j) : (8 - (j))]

__global__ __launch_bounds__(NTHR, 3)
void heatmap_sepconv_kernel(const int* __restrict__ coords,
                            const float* __restrict__ noise,
                            const float* __restrict__ k2d,
                            float* __restrict__ out)
{
    __shared__ float sk[81];
    __shared__ __align__(16) float hs[HROWS * HSTRIDE];  // 36864 B

    const int tid = threadIdx.x;
    const int img = blockIdx.z;
    const int x0 = blockIdx.x * TILE_X;
    const int y0 = blockIdx.y * TILE_Y;

    if (tid < 81) sk[tid] = k2d[tid];
    __syncthreads();

    // 5 scalar symmetric taps (row sums of the 2D kernel).
    float gs[5];
    #pragma unroll
    for (int i = 0; i < 5; i++) {
        float s = 0.f;
        #pragma unroll
        for (int j = 0; j < 9; j++) s += sk[i * 9 + j];
        gs[i] = s;
    }

    const float* __restrict__ np = noise + (size_t)img * (HH * WW);

    // ============ Phase 1: horizontal pass, gmem -> registers -> h smem =======
    // 16 warps sweep rows: warp w does rows w, w+16, w+32, w+48, w+64 (<72).
    {
        const int lane = tid & 31;
        const int w = tid >> 5;              // 0..15
        const int cb = lane << 2;            // local output col group 0..124
        #pragma unroll
        for (int s = 0; s < 5; s++) {
            if (s < 4 || w < HROWS - 64) {   // row < 72
                const int row = s * 16 + w;
                const int gy = y0 - 4 + row;
                float h0 = 0.f, h1 = 0.f, h2 = 0.f, h3 = 0.f;
                if (gy >= 0 && gy < HH) {
                    const float* rowp = np + gy * WW;
                    const int gxl = x0 + cb - 4;
                    const int gxr = x0 + cb + 4;
                    float4 L = (gxl >= 0) ? *(const float4*)(rowp + gxl)
                                          : make_float4(0.f, 0.f, 0.f, 0.f);
                    float4 C = *(const float4*)(rowp + x0 + cb);
                    float4 R = (gxr + 3 < WW) ? *(const float4*)(rowp + gxr)
                                              : make_float4(0.f, 0.f, 0.f, 0.f);
                    float v[12] = {L.x, L.y, L.z, L.w, C.x, C.y, C.z, C.w,
                                   R.x, R.y, R.z, R.w};
                    #pragma unroll
                    for (int j = 0; j < 9; j++) {
                        const float gj = GSYM(j);
                        h0 = fmaf(gj, v[j],     h0);
                        h1 = fmaf(gj, v[j + 1], h1);
                        h2 = fmaf(gj, v[j + 2], h2);
                        h3 = fmaf(gj, v[j + 3], h3);
                    }
                }
                *(float4*)&hs[row * HSTRIDE + cb] = make_float4(h0, h1, h2, h3);
            }
        }
    }
    __syncthreads();

    // ============ Peak injection into the h tile (exact, by linearity) ========
    // Replacing noise[cy][cx] with the peak changes h[cy][c] by delta*g[c-cx+4]
    // for c in [cx-4, cx+4]. 9 threads patch the h row this tile computed.
    if (tid < 9) {
        const int cx = coords[2 * img];
        const int cy = coords[2 * img + 1];
        const int ly = cy - y0 + 4;              // h-tile row of the peak
        const int lcol = cx - 4 + tid - x0;      // h-tile col this thread patches
        if (ly >= 0 && ly < HROWS && lcol >= 0 && lcol < HSTRIDE) {
            float gtap = 0.f;
            #pragma unroll
            for (int jj = 0; jj < 9; jj++) gtap += sk[tid * 9 + jj];
            const float delta = 100.0f / sk[40] - np[cy * WW + cx];
            hs[ly * HSTRIDE + lcol] += delta * gtap;
        }
    }
    __syncthreads();

    // ============ Phase 2: vertical pass from h smem, FFMA2 ===================
    float2 gg[5];
    #pragma unroll
    for (int i = 0; i < 5; i++) gg[i] = make_float2(gs[i], gs[i]);

    const int g  = tid & 63;        // column pair: output cols 2g, 2g+1
    const int ty = tid >> 6;        // 0..7
    const int r0 = ty << 3;         // first output row (8 per thread)

    float2 A[8];
    #pragma unroll
    for (int r = 0; r < 8; r++) A[r] = make_float2(0.f, 0.f);

    // Stream 16 h rows; each LDS.64 is a direct FFMA2 operand (no packing).
    const float* hp = &hs[r0 * HSTRIDE + 2 * g];
    #pragma unroll
    for (int ir = 0; ir < 16; ir++) {
        const float2 hv = *(const float2*)(hp);
        hp += HSTRIDE;
        #pragma unroll
        for (int r = 0; r < 8; r++) {
            const int j = ir - r;
            if (j >= 0 && j <= 8) A[r] = ffma2(GG(j), hv, A[r]);
        }
    }

    // Store: deferred 0.01 scale + ReLU; STG.64 fully coalesced.
    float* op = out + (size_t)img * (HH * WW) + (size_t)(y0 + r0) * WW + x0 + 2 * g;
    #pragma unroll
    for (int r = 0; r < 8; r++) {
        float2 ov = make_float2(fmaxf(A[r].x, 0.f) * 0.01f,
                                fmaxf(A[r].y, 0.f) * 0.01f);
        *(float2*)op = ov;
        op += WW;
    }
}

extern "C" void kernel_launch(void* const* d_in, const int* in_sizes, int n_in,
                              void* d_out, int out_size)
{
    const int* coords = nullptr;
    const float* noise = nullptr;
    const float* k2d = nullptr;
    for (int i = 0; i < n_in; i++) {
        if (in_sizes[i] == 81)            k2d    = (const float*)d_in[i];
        else if (in_sizes[i] == 64*21*2)  coords = (const int*)d_in[i];
        else                              noise  = (const float*)d_in[i];
    }

    dim3 grid(WW / TILE_X, HH / TILE_Y, NIMG);
    heatmap_sepconv_kernel<<<grid, NTHR>>>(coords, noise, k2d, (float*)d_out);
}